// round 1
// baseline (speedup 1.0000x reference)
#include <cuda_runtime.h>
#include <cstddef>

// Problem dims (fixed by setup_inputs): (B=2, C=1, D=160, H=192, W=160) fp32
#define Bn 2
#define Dn 160
#define Hn 192
#define Wn 160
#define Rr 4            // radius, WIN=9
#define HW (Hn*Wn)      // 30720
#define DHW (Dn*HW)     // 4915200
#define NB (Bn*DHW)     // 9830400 voxels total (per channel)
#define NCH 5
#define DSPLIT 4
#define DCHUNK (Dn/DSPLIT)   // 40
#define NPART (Bn*Hn*DSPLIT) // 1536

// Scratch (allowed: __device__ globals, no runtime allocation)
__device__ float g_bufA[NCH * NB];   // ~196.6 MB
__device__ float g_bufB[NCH * NB];   // ~196.6 MB
__device__ double g_part[NPART];

// ---------------------------------------------------------------------------
// Pass 1: 9-tap sum along W (contiguous). Also forms the 5 statistic channels
// I, J, I*I, J*J, I*J on the fly. One block per (b,d,h) row, 160 threads.
// ---------------------------------------------------------------------------
__global__ void __launch_bounds__(Wn) pass_w(const float* __restrict__ I,
                                             const float* __restrict__ J,
                                             float* __restrict__ out) {
    __shared__ float sI[Wn + 2 * Rr];
    __shared__ float sJ[Wn + 2 * Rr];
    const int row  = blockIdx.x;          // 0 .. B*D*H-1
    const int t    = threadIdx.x;         // 0 .. W-1
    const size_t base = (size_t)row * Wn;

    sI[t + Rr] = I[base + t];
    sJ[t + Rr] = J[base + t];
    if (t < Rr) {
        sI[t] = 0.f;            sJ[t] = 0.f;
        sI[Wn + Rr + t] = 0.f;  sJ[Wn + Rr + t] = 0.f;
    }
    __syncthreads();

    float s0 = 0.f, s1 = 0.f, s2 = 0.f, s3 = 0.f, s4 = 0.f;
#pragma unroll
    for (int k = 0; k < 2 * Rr + 1; ++k) {
        const float iv = sI[t + k];
        const float jv = sJ[t + k];
        s0 += iv;
        s1 += jv;
        s2 += iv * iv;
        s3 += jv * jv;
        s4 += iv * jv;
    }
    const size_t gi = base + t;
    out[0 * (size_t)NB + gi] = s0;
    out[1 * (size_t)NB + gi] = s1;
    out[2 * (size_t)NB + gi] = s2;
    out[3 * (size_t)NB + gi] = s3;
    out[4 * (size_t)NB + gi] = s4;
}

// ---------------------------------------------------------------------------
// Pass 2: 9-tap sliding-window sum along H (stride W). One block per
// (c,b,d), 160 threads (one per w) -> fully coalesced reads/writes.
// ---------------------------------------------------------------------------
__global__ void __launch_bounds__(Wn) pass_h(const float* __restrict__ in,
                                             float* __restrict__ out) {
    const int id  = blockIdx.x;            // 0 .. NCH*B*D-1
    const int d   = id % Dn;
    const int rem = id / Dn;
    const int b   = rem % Bn;
    const int c   = rem / Bn;
    const int w   = threadIdx.x;

    const size_t off = (size_t)c * NB + (size_t)b * DHW + (size_t)d * HW + w;
    const float* __restrict__ p = in + off;
    float* __restrict__ q = out + off;

    float s = 0.f;
#pragma unroll
    for (int h = 0; h <= Rr; ++h)          // window for o=0 covers [0..R]
        s += p[(size_t)h * Wn];

    for (int o = 0; o < Hn; ++o) {
        q[(size_t)o * Wn] = s;
        const int ha = o + Rr + 1;
        const int hs = o - Rr;
        if (ha < Hn)  s += p[(size_t)ha * Wn];
        if (hs >= 0)  s -= p[(size_t)hs * Wn];
    }
}

// ---------------------------------------------------------------------------
// Pass 3: 9-tap sliding-window sum along D (stride HW) for all 5 channels,
// fused with the cc epilogue and a per-block reduction. D is split DSPLIT
// ways for occupancy; each chunk re-initializes its window (halo reads).
// Block = 160 threads (one per w); grid = B*H*DSPLIT.
// ---------------------------------------------------------------------------
__global__ void __launch_bounds__(Wn) pass_d_cc(const float* __restrict__ in,
                                                double* __restrict__ partials) {
    const int blk   = blockIdx.x;
    const int chunk = blk % DSPLIT;
    const int id    = blk / DSPLIT;
    const int h     = id % Hn;
    const int b     = id / Hn;
    const int w     = threadIdx.x;

    const float* __restrict__ p = in + (size_t)b * DHW + (size_t)h * Wn + w;

    const int o0 = chunk * DCHUNK;
    const int o1 = o0 + DCHUNK;

    float s0 = 0.f, s1 = 0.f, s2 = 0.f, s3 = 0.f, s4 = 0.f;
#pragma unroll
    for (int d = o0 - Rr; d <= o0 + Rr; ++d) {
        if (d >= 0 && d < Dn) {
            const size_t off = (size_t)d * HW;
            s0 += p[0 * (size_t)NB + off];
            s1 += p[1 * (size_t)NB + off];
            s2 += p[2 * (size_t)NB + off];
            s3 += p[3 * (size_t)NB + off];
            s4 += p[4 * (size_t)NB + off];
        }
    }

    const float inv = 1.0f / 729.0f;
    double acc = 0.0;
    for (int o = o0; o < o1; ++o) {
        const float mu1 = s0 * inv;
        const float mu2 = s1 * inv;
        const float v1  = s2 * inv - mu1 * mu1;
        const float v2  = s3 * inv - mu2 * mu2;
        const float cv  = s4 * inv - mu1 * mu2;
        const float cc  = (cv * cv) / (v1 * v2 + 1e-5f);
        acc += (double)cc;

        const int da = o + Rr + 1;
        const int ds = o - Rr;
        if (da < Dn) {
            const size_t off = (size_t)da * HW;
            s0 += p[0 * (size_t)NB + off];
            s1 += p[1 * (size_t)NB + off];
            s2 += p[2 * (size_t)NB + off];
            s3 += p[3 * (size_t)NB + off];
            s4 += p[4 * (size_t)NB + off];
        }
        if (ds >= 0) {
            const size_t off = (size_t)ds * HW;
            s0 -= p[0 * (size_t)NB + off];
            s1 -= p[1 * (size_t)NB + off];
            s2 -= p[2 * (size_t)NB + off];
            s3 -= p[3 * (size_t)NB + off];
            s4 -= p[4 * (size_t)NB + off];
        }
    }

    // Fixed-order block reduction (deterministic)
    __shared__ double red[Wn];
    red[w] = acc;
    __syncthreads();
    if (w < 32) red[w] += red[w + 128];      // fold 160 -> 128
    __syncthreads();
    for (int s = 64; s > 0; s >>= 1) {
        if (w < s) red[w] += red[w + s];
        __syncthreads();
    }
    if (w == 0) partials[blk] = red[0];
}

// ---------------------------------------------------------------------------
// Final: deterministic fixed-order sum of partials -> -mean(cc)
// ---------------------------------------------------------------------------
__global__ void __launch_bounds__(256) finalize(const double* __restrict__ partials,
                                                float* __restrict__ out) {
    __shared__ double red[256];
    double a = 0.0;
    for (int i = threadIdx.x; i < NPART; i += 256) a += partials[i];
    red[threadIdx.x] = a;
    __syncthreads();
    for (int s = 128; s > 0; s >>= 1) {
        if (threadIdx.x < s) red[threadIdx.x] += red[threadIdx.x + s];
        __syncthreads();
    }
    if (threadIdx.x == 0) out[0] = (float)(-red[0] / (double)NB);
}

extern "C" void kernel_launch(void* const* d_in, const int* in_sizes, int n_in,
                              void* d_out, int out_size) {
    const float* I = (const float*)d_in[0];   // y_true
    const float* J = (const float*)d_in[1];   // y_pred
    float* out = (float*)d_out;

    float* bufA;
    float* bufB;
    double* part;
    cudaGetSymbolAddress((void**)&bufA, g_bufA);
    cudaGetSymbolAddress((void**)&bufB, g_bufB);
    cudaGetSymbolAddress((void**)&part, g_part);

    pass_w<<<Bn * Dn * Hn, Wn>>>(I, J, bufA);
    pass_h<<<NCH * Bn * Dn, Wn>>>(bufA, bufB);
    pass_d_cc<<<NPART, Wn>>>(bufB, part);
    finalize<<<1, 256>>>(part, out);
}